// round 1
// baseline (speedup 1.0000x reference)
#include <cuda_runtime.h>

#define BB 256
#define AA 128
#define DD 5
#define FATOM 256
#define FBOND 64
#define FTOT 320   // FATOM + FBOND
#define CC 256
#define NROWS (BB * AA)
#define TILE_M 16

// Scratch: per-deg compacted row lists (no device allocation allowed).
__device__ int g_count[DD];
__device__ int g_rows[DD * NROWS];

// Kernel A: zero the output (96% of rows stay zero) + reset counters.
__global__ void zero_out_kernel(float4* __restrict__ out, int n4) {
    if (blockIdx.x == 0 && threadIdx.x < DD) g_count[threadIdx.x] = 0;
    float4 z = make_float4(0.f, 0.f, 0.f, 0.f);
    int stride = gridDim.x * blockDim.x;
    for (int i = blockIdx.x * blockDim.x + threadIdx.x; i < n4; i += stride)
        out[i] = z;
}

// Kernel B: compute deg per row; append rows with deg < 5 to their deg-list.
// Atomic append order varies, but each row is processed exactly once and
// independently, so the final output is deterministic.
__global__ void classify_kernel(const int* __restrict__ edges) {
    int row = blockIdx.x * blockDim.x + threadIdx.x;
    if (row >= NROWS) return;
    int deg = 0;
#pragma unroll
    for (int d = 0; d < DD; d++) deg += (edges[row * DD + d] != -1);
    if (deg < DD) {
        int pos = atomicAdd(&g_count[deg], 1);
        g_rows[deg * NROWS + pos] = row;
    }
}

// Kernel C: per-deg grouped GEMM.
//   feat[row] = [atoms[row] + sum_{e>=0} atoms[b,e]  |  sum_d bonds[row,d,:]]
//   out[row]  = relu(feat @ W[deg] + bias[deg])
// Block = 256 threads (one per output column c), TILE_M rows per tile,
// feat staged in smem, W[deg] columns streamed coalesced from L2.
__global__ void __launch_bounds__(256) gemm_kernel(
    const float* __restrict__ atoms, const float* __restrict__ bonds,
    const int* __restrict__ edges, const float* __restrict__ W,
    const float* __restrict__ bias, float* __restrict__ out)
{
    __shared__ float feat[TILE_M][FTOT];  // 16 * 320 * 4 = 20 KB, 16B-aligned rows
    const int deg = blockIdx.y;
    const int count = g_count[deg];
    const int tid = threadIdx.x;
    const float* Wd = W + deg * FTOT * CC;
    const float bv = bias[deg * CC + tid];

    for (int tile = blockIdx.x; tile * TILE_M < count; tile += gridDim.x) {
        const int base = tile * TILE_M;
        const int nrows = min(TILE_M, count - base);

        __syncthreads();  // previous iteration's feat reads done before rewrite

        // ---- Build feat tile ----
        for (int r = 0; r < nrows; r++) {
            const int row = g_rows[deg * NROWS + base + r];
            const int bidx = row >> 7;  // row / AA
            // atom part: self + valid neighbors (all 256 threads, f = tid)
            float v = atoms[row * FATOM + tid];
#pragma unroll
            for (int d = 0; d < DD; d++) {
                int e = edges[row * DD + d];
                if (e >= 0) v += atoms[(bidx * AA + e) * FATOM + tid];
            }
            feat[r][tid] = v;
            // bond part: unconditional sum over all D (threads 0..63)
            if (tid < FBOND) {
                float s = 0.f;
#pragma unroll
                for (int d = 0; d < DD; d++)
                    s += bonds[(row * DD + d) * FBOND + tid];
                feat[r][FATOM + tid] = s;
            }
        }
        __syncthreads();

        // ---- GEMM: acc[r] = bias + feat[r] . W[deg][:, c] ----
        float acc[TILE_M];
#pragma unroll
        for (int r = 0; r < TILE_M; r++) acc[r] = bv;

        const float* wc = Wd + tid;  // column c = tid, stride CC over f
        for (int f = 0; f < FTOT; f += 4) {
            float w0 = wc[(f + 0) * CC];
            float w1 = wc[(f + 1) * CC];
            float w2 = wc[(f + 2) * CC];
            float w3 = wc[(f + 3) * CC];
#pragma unroll
            for (int r = 0; r < TILE_M; r++) {
                float4 fv = *reinterpret_cast<const float4*>(&feat[r][f]);
                acc[r] += fv.x * w0;
                acc[r] += fv.y * w1;
                acc[r] += fv.z * w2;
                acc[r] += fv.w * w3;
            }
        }

        // ---- Epilogue: relu + scatter to output rows ----
        for (int r = 0; r < nrows; r++) {
            const int row = g_rows[deg * NROWS + base + r];
            out[row * CC + tid] = fmaxf(acc[r], 0.f);
        }
    }
}

extern "C" void kernel_launch(void* const* d_in, const int* in_sizes, int n_in,
                              void* d_out, int out_size) {
    const float* atoms = (const float*)d_in[0];   // (B, A, FA) f32
    const float* bonds = (const float*)d_in[1];   // (B, A, D, FB) f32
    const int*   edges = (const int*)d_in[2];     // (B, A, D) i32
    const float* W     = (const float*)d_in[3];   // (D, FA+FB, C) f32
    const float* bias  = (const float*)d_in[4];   // (D, C) f32
    float* out = (float*)d_out;                   // (B, A, C) f32

    int n4 = out_size / 4;
    zero_out_kernel<<<1024, 256>>>((float4*)out, n4);
    classify_kernel<<<(NROWS + 255) / 256, 256>>>(edges);
    gemm_kernel<<<dim3(128, DD), 256>>>(atoms, bonds, edges, W, bias, out);
}

// round 2
// speedup vs baseline: 1.3166x; 1.3166x over previous
#include <cuda_runtime.h>

#define BB 256
#define AA 128
#define DD 5
#define FATOM 256
#define FBOND 64
#define FTOT 320   // FATOM + FBOND
#define CC 256
#define NROWS (BB * AA)
#define TILE_M 8
#define TILES_X 256

// Scratch (no device allocation allowed anywhere).
__device__ int g_count[DD];
__device__ int g_rows[DD * NROWS];

// ---------------- packed f32x2 helpers ----------------
__device__ __forceinline__ unsigned long long pack2(float lo, float hi) {
    unsigned long long r;
    asm("mov.b64 %0, {%1, %2};" : "=l"(r) : "f"(lo), "f"(hi));
    return r;
}
__device__ __forceinline__ void unpack2(unsigned long long v, float& lo, float& hi) {
    asm("mov.b64 {%0, %1}, %2;" : "=f"(lo), "=f"(hi) : "l"(v));
}
__device__ __forceinline__ unsigned long long fma2(unsigned long long a,
                                                   unsigned long long b,
                                                   unsigned long long c) {
    unsigned long long d;
    asm("fma.rn.f32x2 %0, %1, %2, %3;" : "=l"(d) : "l"(a), "l"(b), "l"(c));
    return d;
}

// Kernel A: zero the 32MB output (~96% of rows stay zero) + reset counters.
__global__ void __launch_bounds__(256) zero_out_kernel(float4* __restrict__ out) {
    if (blockIdx.x == 0 && threadIdx.x < DD) g_count[threadIdx.x] = 0;
    const float4 z = make_float4(0.f, 0.f, 0.f, 0.f);
    // exact: 2048 blocks * 256 threads * 4 = 2,097,152 = out_size/4
    int base = (blockIdx.x * 256 + threadIdx.x) * 4;
    out[base + 0] = z;
    out[base + 1] = z;
    out[base + 2] = z;
    out[base + 3] = z;
}

// Kernel B: compute deg per row; append rows with deg < 5 to their deg-list.
// Append order varies run-to-run but each row is written exactly once,
// independently -> deterministic final output.
__global__ void classify_kernel(const int* __restrict__ edges) {
    int row = blockIdx.x * blockDim.x + threadIdx.x;
    if (row >= NROWS) return;
    int deg = 0;
#pragma unroll
    for (int d = 0; d < DD; d++) deg += (edges[row * DD + d] != -1);
    if (deg < DD) {
        int pos = atomicAdd(&g_count[deg], 1);
        g_rows[deg * NROWS + pos] = row;
    }
}

// Kernel C: per-deg grouped GEMM.
//   feat[row] = [atoms[row] + sum_{e>=0} atoms[b,e]  |  sum_d bonds[row,d,:]]
//   out[row]  = relu(feat @ W[deg] + bias[deg])
// Block = 256 threads. Tile = TILE_M(8) rows x CC(256) cols.
// Feat build: warp w gathers row w (all loads in flight, float4).
// GEMM: thread = (col-pair cp in 0..127, row-group rg in 0..1), computes
//       2 adjacent C columns for 4 rows via packed fma.rn.f32x2.
__global__ void __launch_bounds__(256) gemm_kernel(
    const float4* __restrict__ atoms4, const float4* __restrict__ bonds4,
    const int* __restrict__ edges, const float* __restrict__ W,
    const float* __restrict__ bias, float* __restrict__ out)
{
    __shared__ float feat[TILE_M][FTOT];  // 8 * 320 * 4 = 10 KB
    const int deg = blockIdx.y;
    const int count = g_count[deg];
    if (count == 0) return;

    const int tid  = threadIdx.x;
    const int wid  = tid >> 5;
    const int lane = tid & 31;
    const int cp   = tid & 127;   // column pair -> cols 2cp, 2cp+1
    const int rg   = tid >> 7;    // row group: rows rg*4 .. rg*4+3
    const float* Wd = W + deg * FTOT * CC;
    const unsigned long long bv2 =
        *reinterpret_cast<const unsigned long long*>(&bias[deg * CC + 2 * cp]);

    for (int tile = blockIdx.x; tile * TILE_M < count; tile += gridDim.x) {
        const int base  = tile * TILE_M;
        const int nrows = min(TILE_M, count - base);

        __syncthreads();  // protect feat from previous iteration readers

        // ---- Feat build: warp 'wid' builds row 'wid' ----
        if (wid < nrows) {
            const int row   = g_rows[deg * NROWS + base + wid];
            const int bbase = (row >> 7) << 7;  // b * AA
            int e[DD];
#pragma unroll
            for (int d = 0; d < DD; d++) e[d] = edges[row * DD + d];

            // atom part: 256 floats = 64 float4; lanes cover 32, k=0..1
#pragma unroll
            for (int k = 0; k < 2; k++) {
                const int f4 = lane + 32 * k;            // float4 index in row
                float4 v = atoms4[row * 64 + f4];
#pragma unroll
                for (int d = 0; d < DD; d++) {
                    if (e[d] >= 0) {
                        float4 nv = atoms4[(bbase + e[d]) * 64 + f4];
                        v.x += nv.x; v.y += nv.y; v.z += nv.z; v.w += nv.w;
                    }
                }
                *reinterpret_cast<float4*>(&feat[wid][f4 * 4]) = v;
            }
            // bond part: 64 floats = 16 float4; lanes 0..15
            if (lane < 16) {
                float4 s = make_float4(0.f, 0.f, 0.f, 0.f);
#pragma unroll
                for (int d = 0; d < DD; d++) {
                    float4 bvv = bonds4[(row * DD + d) * 16 + lane];
                    s.x += bvv.x; s.y += bvv.y; s.z += bvv.z; s.w += bvv.w;
                }
                *reinterpret_cast<float4*>(&feat[wid][FATOM + lane * 4]) = s;
            }
        }
        __syncthreads();

        // ---- GEMM: acc2[r] over f, packed 2 columns per thread ----
        unsigned long long acc[4];
#pragma unroll
        for (int r = 0; r < 4; r++) acc[r] = bv2;

        const unsigned long long* wc =
            reinterpret_cast<const unsigned long long*>(Wd + 2 * cp);
        // wc[(f * CC) / 2] == W[f][2cp..2cp+1]; stride CC/2 in ull units
        for (int f = 0; f < FTOT; f += 4) {
            unsigned long long w0 = wc[(f + 0) * (CC / 2)];
            unsigned long long w1 = wc[(f + 1) * (CC / 2)];
            unsigned long long w2 = wc[(f + 2) * (CC / 2)];
            unsigned long long w3 = wc[(f + 3) * (CC / 2)];
#pragma unroll
            for (int r = 0; r < 4; r++) {
                const float4 fv =
                    *reinterpret_cast<const float4*>(&feat[rg * 4 + r][f]);
                acc[r] = fma2(pack2(fv.x, fv.x), w0, acc[r]);
                acc[r] = fma2(pack2(fv.y, fv.y), w1, acc[r]);
                acc[r] = fma2(pack2(fv.z, fv.z), w2, acc[r]);
                acc[r] = fma2(pack2(fv.w, fv.w), w3, acc[r]);
            }
        }

        // ---- Epilogue: relu + scatter ----
#pragma unroll
        for (int r = 0; r < 4; r++) {
            const int ri = rg * 4 + r;
            if (ri < nrows) {
                const int row = g_rows[deg * NROWS + base + ri];
                float lo, hi;
                unpack2(acc[r], lo, hi);
                float2 o = make_float2(fmaxf(lo, 0.f), fmaxf(hi, 0.f));
                *reinterpret_cast<float2*>(&out[row * CC + 2 * cp]) = o;
            }
        }
    }
}

extern "C" void kernel_launch(void* const* d_in, const int* in_sizes, int n_in,
                              void* d_out, int out_size) {
    const float* atoms = (const float*)d_in[0];   // (B, A, FA) f32
    const float* bonds = (const float*)d_in[1];   // (B, A, D, FB) f32
    const int*   edges = (const int*)d_in[2];     // (B, A, D) i32
    const float* W     = (const float*)d_in[3];   // (D, FA+FB, C) f32
    const float* bias  = (const float*)d_in[4];   // (D, C) f32
    float* out = (float*)d_out;                   // (B, A, C) f32

    zero_out_kernel<<<2048, 256>>>((float4*)out);  // 2048*256*4*16B = 32MB exact
    classify_kernel<<<(NROWS + 255) / 256, 256>>>(edges);
    gemm_kernel<<<dim3(TILES_X, DD), 256>>>((const float4*)atoms,
                                            (const float4*)bonds,
                                            edges, W, bias, out);
}

// round 3
// speedup vs baseline: 1.6378x; 1.2440x over previous
#include <cuda_runtime.h>

#define BB 256
#define AA 128
#define DD 5
#define FATOM 256
#define FBOND 64
#define FTOT 320   // FATOM + FBOND
#define CC 256
#define NROWS (BB * AA)
#define TILE_M 16
#define TILES_X 80

// Scratch (no device allocation allowed anywhere).
__device__ int g_count[DD];
__device__ int g_rows[DD * NROWS];

// ---------------- packed f32x2 helpers ----------------
__device__ __forceinline__ unsigned long long pack2(float lo, float hi) {
    unsigned long long r;
    asm("mov.b64 %0, {%1, %2};" : "=l"(r) : "f"(lo), "f"(hi));
    return r;
}
__device__ __forceinline__ void unpack2(unsigned long long v, float& lo, float& hi) {
    asm("mov.b64 {%0, %1}, %2;" : "=f"(lo), "=f"(hi) : "l"(v));
}
__device__ __forceinline__ unsigned long long fma2(unsigned long long a,
                                                   unsigned long long b,
                                                   unsigned long long c) {
    unsigned long long d;
    asm("fma.rn.f32x2 %0, %1, %2, %3;" : "=l"(d) : "l"(a), "l"(b), "l"(c));
    return d;
}

// Kernel A: zero the 32MB output (~96% of rows stay zero) + reset counters.
// COALESCED: consecutive lanes write consecutive float4s; 4 independent
// full-width stores per thread (MLP_p1 = 4).
__global__ void __launch_bounds__(256) zero_out_kernel(float4* __restrict__ out) {
    if (blockIdx.x == 0 && threadIdx.x < DD) g_count[threadIdx.x] = 0;
    const float4 z = make_float4(0.f, 0.f, 0.f, 0.f);
    const int gid = blockIdx.x * 256 + threadIdx.x;   // 0 .. 524287
    const int stride = 2048 * 256;                    // total threads
    out[gid + 0 * stride] = z;
    out[gid + 1 * stride] = z;
    out[gid + 2 * stride] = z;
    out[gid + 3 * stride] = z;
}

// Kernel B: compute deg per row; append rows with deg < 5 to their deg-list.
// Append order varies run-to-run but each row is processed exactly once,
// independently -> deterministic final output.
__global__ void classify_kernel(const int* __restrict__ edges) {
    int row = blockIdx.x * blockDim.x + threadIdx.x;
    if (row >= NROWS) return;
    int deg = 0;
#pragma unroll
    for (int d = 0; d < DD; d++) deg += (edges[row * DD + d] != -1);
    if (deg < DD) {
        int pos = atomicAdd(&g_count[deg], 1);
        g_rows[deg * NROWS + pos] = row;
    }
}

// Kernel C: per-deg grouped GEMM.
//   feat[row] = [atoms[row] + sum_{e>=0} atoms[b,e]  |  sum_d bonds[row,d,:]]
//   out[row]  = relu(feat @ W[deg] + bias[deg])
// Block = 256 threads. Tile = TILE_M(16) rows x CC(256) cols.
// Thread = (col-pair cp in 0..127, row-group rg in 0..1); each thread
// computes 2 adjacent C columns for 8 rows via packed fma.rn.f32x2.
// W loaded twice per tile (rg redundancy) -> 40KB L2 traffic per row.
__global__ void __launch_bounds__(256) gemm_kernel(
    const float4* __restrict__ atoms4, const float4* __restrict__ bonds4,
    const int* __restrict__ edges, const float* __restrict__ W,
    const float* __restrict__ bias, float* __restrict__ out)
{
    __shared__ float feat[TILE_M][FTOT];  // 16 * 320 * 4 = 20 KB
    const int deg = blockIdx.y;
    const int count = g_count[deg];
    if (count == 0) return;

    const int tid  = threadIdx.x;
    const int wid  = tid >> 5;
    const int lane = tid & 31;
    const int cp   = tid & 127;   // column pair -> cols 2cp, 2cp+1
    const int rg   = tid >> 7;    // row group: rows rg*8 .. rg*8+7
    const float* Wd = W + deg * FTOT * CC;
    const unsigned long long bv2 =
        *reinterpret_cast<const unsigned long long*>(&bias[deg * CC + 2 * cp]);

    for (int tile = blockIdx.x; tile * TILE_M < count; tile += gridDim.x) {
        const int base  = tile * TILE_M;
        const int nrows = min(TILE_M, count - base);

        __syncthreads();  // protect feat from previous iteration readers

        // ---- Feat build: warp 'wid' builds rows wid and wid+8 ----
#pragma unroll
        for (int rr = 0; rr < 2; rr++) {
            const int r = wid + rr * 8;
            if (r < nrows) {
                const int row   = g_rows[deg * NROWS + base + r];
                const int bbase = (row >> 7) << 7;  // b * AA
                int e[DD];
#pragma unroll
                for (int d = 0; d < DD; d++) e[d] = edges[row * DD + d];

                // atom part: 256 floats = 64 float4; lanes cover 32, k=0..1
#pragma unroll
                for (int k = 0; k < 2; k++) {
                    const int f4 = lane + 32 * k;
                    float4 v = atoms4[row * 64 + f4];
#pragma unroll
                    for (int d = 0; d < DD; d++) {
                        if (e[d] >= 0) {
                            float4 nv = atoms4[(bbase + e[d]) * 64 + f4];
                            v.x += nv.x; v.y += nv.y; v.z += nv.z; v.w += nv.w;
                        }
                    }
                    *reinterpret_cast<float4*>(&feat[r][f4 * 4]) = v;
                }
                // bond part: 64 floats = 16 float4; lanes 0..15
                if (lane < 16) {
                    float4 s = make_float4(0.f, 0.f, 0.f, 0.f);
#pragma unroll
                    for (int d = 0; d < DD; d++) {
                        float4 bvv = bonds4[(row * DD + d) * 16 + lane];
                        s.x += bvv.x; s.y += bvv.y; s.z += bvv.z; s.w += bvv.w;
                    }
                    *reinterpret_cast<float4*>(&feat[r][FATOM + lane * 4]) = s;
                }
            }
        }
        __syncthreads();

        // ---- GEMM: 8 rows x 2 cols per thread, packed fma.rn.f32x2 ----
        unsigned long long acc[8];
#pragma unroll
        for (int r = 0; r < 8; r++) acc[r] = bv2;

        const unsigned long long* wc =
            reinterpret_cast<const unsigned long long*>(Wd + 2 * cp);
        // wc[f * (CC/2)] == W[f][2cp..2cp+1]
        for (int f = 0; f < FTOT; f += 4) {
            unsigned long long w0 = wc[(f + 0) * (CC / 2)];
            unsigned long long w1 = wc[(f + 1) * (CC / 2)];
            unsigned long long w2 = wc[(f + 2) * (CC / 2)];
            unsigned long long w3 = wc[(f + 3) * (CC / 2)];
#pragma unroll
            for (int r = 0; r < 8; r++) {
                const float4 fv =
                    *reinterpret_cast<const float4*>(&feat[rg * 8 + r][f]);
                acc[r] = fma2(pack2(fv.x, fv.x), w0, acc[r]);
                acc[r] = fma2(pack2(fv.y, fv.y), w1, acc[r]);
                acc[r] = fma2(pack2(fv.z, fv.z), w2, acc[r]);
                acc[r] = fma2(pack2(fv.w, fv.w), w3, acc[r]);
            }
        }

        // ---- Epilogue: relu + scatter ----
#pragma unroll
        for (int r = 0; r < 8; r++) {
            const int ri = rg * 8 + r;
            if (ri < nrows) {
                const int row = g_rows[deg * NROWS + base + ri];
                float lo, hi;
                unpack2(acc[r], lo, hi);
                float2 o = make_float2(fmaxf(lo, 0.f), fmaxf(hi, 0.f));
                *reinterpret_cast<float2*>(&out[row * CC + 2 * cp]) = o;
            }
        }
    }
}

extern "C" void kernel_launch(void* const* d_in, const int* in_sizes, int n_in,
                              void* d_out, int out_size) {
    const float* atoms = (const float*)d_in[0];   // (B, A, FA) f32
    const float* bonds = (const float*)d_in[1];   // (B, A, D, FB) f32
    const int*   edges = (const int*)d_in[2];     // (B, A, D) i32
    const float* W     = (const float*)d_in[3];   // (D, FA+FB, C) f32
    const float* bias  = (const float*)d_in[4];   // (D, C) f32
    float* out = (float*)d_out;                   // (B, A, C) f32

    zero_out_kernel<<<2048, 256>>>((float4*)out);  // coalesced, 32MB exact
    classify_kernel<<<(NROWS + 255) / 256, 256>>>(edges);
    gemm_kernel<<<dim3(TILES_X, DD), 256>>>((const float4*)atoms,
                                            (const float4*)bonds,
                                            edges, W, bias, out);
}